// round 4
// baseline (speedup 1.0000x reference)
#include <cuda_runtime.h>

// CAN co-action unit: per-sample 2-layer MLP, D=16, N=50, B=16384.
// R=4 rows/thread (13 threads/sample), x+out staged dense through SMEM
// (padded stride 20 words -> conflict-free strided LDS/STS), weights via
// broadcast LDS, compute in packed f32x2 FFMA2.

#define D 16
#define N 50
#define PARAMS 544            // 2*(256+16)
#define PSTRIDE 552           // padded param stride, words (16B aligned, %32==8)
#define XSTRIDE 20            // padded x row stride, words (16B aligned, %8==4)
#define SPC 16                // samples per CTA
#define TPS 13                // threads per sample (ceil(52/4))
#define THREADS (SPC * TPS)   // 208
#define CTA_ROWS (SPC * N)    // 800
#define SP_WORDS (SPC * PSTRIDE)     // 8832
#define SX_WORDS (CTA_ROWS * XSTRIDE) // 16000
#define SMEM_BYTES ((SP_WORDS + SX_WORDS) * 4)  // 99328

__device__ __forceinline__ unsigned long long splat2(float x) {
    unsigned long long r; unsigned u = __float_as_uint(x);
    asm("mov.b64 %0, {%1, %1};" : "=l"(r) : "r"(u));
    return r;
}
__device__ __forceinline__ void ffma2(unsigned long long& d,
                                      unsigned long long a, unsigned long long b) {
    asm("fma.rn.f32x2 %0, %1, %2, %0;" : "+l"(d) : "l"(a), "l"(b));
}
__device__ __forceinline__ void unpack2(unsigned long long v, float& lo, float& hi) {
    unsigned a, b;
    asm("mov.b64 {%0, %1}, %2;" : "=r"(a), "=r"(b) : "l"(v));
    lo = __uint_as_float(a); hi = __uint_as_float(b);
}

__global__ __launch_bounds__(THREADS, 2) void can_kernel(
    const float* __restrict__ user_emb,
    const float* __restrict__ item_emb,
    float* __restrict__ out)
{
    extern __shared__ float smem[];
    float* sp = smem;             // params, padded
    float* sx = smem + SP_WORDS;  // x tile (later reused as out tile), padded

    const int t = threadIdx.x;

    // ---- Stage params: 16 samples x 136 float4, dense LDG -> padded STS.
    {
        const float4* src = (const float4*)(item_emb + (size_t)blockIdx.x * SPC * PARAMS);
        for (int i = t; i < SPC * (PARAMS / 4); i += THREADS) {
            int si = i / (PARAMS / 4);
            int wi = i - si * (PARAMS / 4);
            *(float4*)(sp + si * PSTRIDE + wi * 4) = src[i];
        }
    }
    // ---- Stage x: 800 rows x 4 float4, dense LDG -> padded STS.
    {
        const float4* src = (const float4*)(user_emb + (size_t)blockIdx.x * CTA_ROWS * D);
        for (int i = t; i < CTA_ROWS * 4; i += THREADS) {
            int row = i >> 2, q = i & 3;
            *(float4*)(sx + row * XSTRIDE + q * 4) = src[i];
        }
    }
    __syncthreads();

    const int s = t / TPS;          // sample in CTA
    const int g = t - s * TPS;      // row group 0..12
    const float* p  = sp + s * PSTRIDE;
    const float* xt = sx + s * N * XSTRIDE;

    // Rows handled: g + 13k, k=0..3 (virtual rows 50,51 clamped, not stored)
    int   rrow[4];
    bool  wr[4];
    #pragma unroll
    for (int k = 0; k < 4; k++) {
        int r = g + 13 * k;
        wr[k]   = (r < N);
        rrow[k] = wr[k] ? r : (N - 1);
    }

    // ======== Layer 1: acc[r][e] = x[r,:] @ W0[:,e] + b0, f32x2 packed ========
    unsigned long long acc[4][8];
    {
        const ulonglong2* bp = (const ulonglong2*)(p + 256);
        #pragma unroll
        for (int j = 0; j < 4; j++) {
            ulonglong2 bv = bp[j];
            #pragma unroll
            for (int k = 0; k < 4; k++) { acc[k][2*j] = bv.x; acc[k][2*j+1] = bv.y; }
        }
        #pragma unroll
        for (int d = 0; d < D; d++) {
            const ulonglong2* wrow = (const ulonglong2*)(p + d * D);
            ulonglong2 wA = wrow[0], wB = wrow[1], wC = wrow[2], wD_ = wrow[3];
            #pragma unroll
            for (int k = 0; k < 4; k++) {
                unsigned long long xs = splat2(xt[rrow[k] * XSTRIDE + d]);  // LDS.32
                ffma2(acc[k][0], xs, wA.x); ffma2(acc[k][1], xs, wA.y);
                ffma2(acc[k][2], xs, wB.x); ffma2(acc[k][3], xs, wB.y);
                ffma2(acc[k][4], xs, wC.x); ffma2(acc[k][5], xs, wC.y);
                ffma2(acc[k][6], xs, wD_.x); ffma2(acc[k][7], xs, wD_.y);
            }
        }
    }
    // relu -> h scalars
    float h[4][D];
    #pragma unroll
    for (int k = 0; k < 4; k++)
        #pragma unroll
        for (int j = 0; j < 8; j++) {
            float lo, hi; unpack2(acc[k][j], lo, hi);
            h[k][2*j]   = fmaxf(lo, 0.0f);
            h[k][2*j+1] = fmaxf(hi, 0.0f);
        }

    // All layer-1 x reads done before anyone overwrites sx with outputs.
    __syncthreads();

    // ======== Layer 2 in two 8-col groups, store relu to sx (reused) ========
    #pragma unroll
    for (int cg = 0; cg < 2; cg++) {
        unsigned long long a2[4][4];
        {
            const ulonglong2* bp = (const ulonglong2*)(p + 528 + cg * 8);
            #pragma unroll
            for (int j = 0; j < 2; j++) {
                ulonglong2 bv = bp[j];
                #pragma unroll
                for (int k = 0; k < 4; k++) { a2[k][2*j] = bv.x; a2[k][2*j+1] = bv.y; }
            }
        }
        #pragma unroll
        for (int d = 0; d < D; d++) {
            const ulonglong2* wrow = (const ulonglong2*)(p + 272 + d * D + cg * 8);
            ulonglong2 wA = wrow[0], wB = wrow[1];
            #pragma unroll
            for (int k = 0; k < 4; k++) {
                unsigned long long xs = splat2(h[k][d]);
                ffma2(a2[k][0], xs, wA.x); ffma2(a2[k][1], xs, wA.y);
                ffma2(a2[k][2], xs, wB.x); ffma2(a2[k][3], xs, wB.y);
            }
        }
        #pragma unroll
        for (int k = 0; k < 4; k++) {
            if (!wr[k]) continue;
            float* dst = sx + (s * N + g + 13 * k) * XSTRIDE + cg * 8;
            float v0, v1, v2, v3, v4, v5, v6, v7;
            unpack2(a2[k][0], v0, v1); unpack2(a2[k][1], v2, v3);
            unpack2(a2[k][2], v4, v5); unpack2(a2[k][3], v6, v7);
            float4 o0 = { fmaxf(v0,0.f), fmaxf(v1,0.f), fmaxf(v2,0.f), fmaxf(v3,0.f) };
            float4 o1 = { fmaxf(v4,0.f), fmaxf(v5,0.f), fmaxf(v6,0.f), fmaxf(v7,0.f) };
            *(float4*)(dst)     = o0;   // STS.128, lanes stride 20 words: conflict-free
            *(float4*)(dst + 4) = o1;
        }
    }
    __syncthreads();

    // ---- Dense write-out: padded LDS -> coalesced STG.128.
    {
        float4* dst = (float4*)(out + (size_t)blockIdx.x * CTA_ROWS * D);
        for (int i = t; i < CTA_ROWS * 4; i += THREADS) {
            int row = i >> 2, q = i & 3;
            dst[i] = *(const float4*)(sx + row * XSTRIDE + q * 4);
        }
    }
}

extern "C" void kernel_launch(void* const* d_in, const int* in_sizes, int n_in,
                              void* d_out, int out_size) {
    const float* user_emb = (const float*)d_in[0];
    const float* item_emb = (const float*)d_in[1];
    float* out = (float*)d_out;
    const int B = in_sizes[1] / PARAMS;   // 16384
    cudaFuncSetAttribute(can_kernel, cudaFuncAttributeMaxDynamicSharedMemorySize,
                         SMEM_BYTES);
    can_kernel<<<B / SPC, THREADS, SMEM_BYTES>>>(user_emb, item_emb, out);
}

// round 5
// speedup vs baseline: 1.1928x; 1.1928x over previous
#include <cuda_runtime.h>

// CAN co-action unit: per-sample 2-layer MLP, D=16, N=50, B=16384.
// R3 structure (224 thr, 8 samples/CTA, 2 rows/thread, x in regs) with:
//  - x and out staged dense through an XOR-swizzled smem tile (kills the 16x
//    LDG/STG wavefront amplification of strided row-per-thread gmem access)
//  - packed f32x2 FFMA2 compute (halves FMA issue)
// smem 43.3KB static -> 3 CTAs/SM, 21 warps, regs capped at 97.

#define D 16
#define N 50
#define PARAMS 544            // 2*(256+16)
#define PSTRIDE 552           // padded param stride, words
#define SPC 8                 // samples per CTA
#define TPS 25                // threads per sample (2 rows each)
#define THREADS 224           // 7 warps
#define ACTIVE (SPC * TPS)    // 200
#define CTA_ROWS (SPC * N)    // 400
#define PWORDS (SPC * PSTRIDE)   // 4416
#define XWORDS (CTA_ROWS * D)    // 6400

// Swizzled x-tile addressing: row stride 16 words, float4 chunk permuted so
// both dense (row-major sweep) and strided (row-per-lane) accesses sit at the
// 4-wavefront data floor.
__device__ __forceinline__ int xaddr(int row, int q) {
    int c = (q ^ (row & 3) ^ ((row >> 2) & 1)) & 3;
    return row * D + c * 4;
}

__device__ __forceinline__ unsigned long long splat2(float x) {
    unsigned long long r; unsigned u = __float_as_uint(x);
    asm("mov.b64 %0, {%1, %1};" : "=l"(r) : "r"(u));
    return r;
}
__device__ __forceinline__ void ffma2(unsigned long long& d,
                                      unsigned long long a, unsigned long long b) {
    asm("fma.rn.f32x2 %0, %1, %2, %0;" : "+l"(d) : "l"(a), "l"(b));
}
__device__ __forceinline__ void unpack2(unsigned long long v, float& lo, float& hi) {
    unsigned a, b;
    asm("mov.b64 {%0, %1}, %2;" : "=r"(a), "=r"(b) : "l"(v));
    lo = __uint_as_float(a); hi = __uint_as_float(b);
}

__global__ __launch_bounds__(THREADS, 3) void can_kernel(
    const float* __restrict__ user_emb,
    const float* __restrict__ item_emb,
    float* __restrict__ out)
{
    __shared__ float sp[PWORDS];   // params, padded stride 552
    __shared__ float sx[XWORDS];   // x tile, swizzled; reused for out tile

    const int t = threadIdx.x;

    // ---- Stage params: dense LDG.128 -> padded STS.128.
    {
        const float4* src = (const float4*)(item_emb + (size_t)blockIdx.x * SPC * PARAMS);
        for (int i = t; i < SPC * (PARAMS / 4); i += THREADS) {
            int si = i / (PARAMS / 4);
            int wi = i - si * (PARAMS / 4);
            *(float4*)(sp + si * PSTRIDE + wi * 4) = src[i];
        }
    }
    // ---- Stage x: dense LDG.128 -> swizzled STS.128 (4 wf each, floor).
    {
        const float4* src = (const float4*)(user_emb + (size_t)blockIdx.x * CTA_ROWS * D);
        for (int i = t; i < CTA_ROWS * 4; i += THREADS) {
            int row = i >> 2, q = i & 3;
            *(float4*)(sx + xaddr(row, q)) = src[i];
        }
    }
    __syncthreads();

    if (t < ACTIVE) {
        const int s = t / TPS;
        const int j = t - s * TPS;
        const float* p = sp + s * PSTRIDE;
        const int r0 = s * N + j;        // local rows: j and j+25 of sample s
        const int r1 = r0 + TPS;

        // x rows into registers (strided LDS.128, 4-way = data floor).
        float x0[D], x1[D];
        #pragma unroll
        for (int q = 0; q < 4; q++) {
            float4 a = *(const float4*)(sx + xaddr(r0, q));
            float4 b = *(const float4*)(sx + xaddr(r1, q));
            x0[4*q+0]=a.x; x0[4*q+1]=a.y; x0[4*q+2]=a.z; x0[4*q+3]=a.w;
            x1[4*q+0]=b.x; x1[4*q+1]=b.y; x1[4*q+2]=b.z; x1[4*q+3]=b.w;
        }

        unsigned long long a0[8], a1[8];

        // ---- Layer 1: relu(x W0 + b0). W0=p[0..255], b0=p[256..271].
        {
            const ulonglong2* bp = (const ulonglong2*)(p + 256);
            #pragma unroll
            for (int h = 0; h < 4; h++) {
                ulonglong2 bv = bp[h];
                a0[2*h]=bv.x; a0[2*h+1]=bv.y;
                a1[2*h]=bv.x; a1[2*h+1]=bv.y;
            }
            #pragma unroll
            for (int d = 0; d < D; d++) {
                const ulonglong2* wr = (const ulonglong2*)(p + d * D);
                ulonglong2 wA = wr[0], wB = wr[1], wC = wr[2], wE = wr[3];
                unsigned long long u0 = splat2(x0[d]), u1 = splat2(x1[d]);
                ffma2(a0[0],u0,wA.x); ffma2(a1[0],u1,wA.x);
                ffma2(a0[1],u0,wA.y); ffma2(a1[1],u1,wA.y);
                ffma2(a0[2],u0,wB.x); ffma2(a1[2],u1,wB.x);
                ffma2(a0[3],u0,wB.y); ffma2(a1[3],u1,wB.y);
                ffma2(a0[4],u0,wC.x); ffma2(a1[4],u1,wC.x);
                ffma2(a0[5],u0,wC.y); ffma2(a1[5],u1,wC.y);
                ffma2(a0[6],u0,wE.x); ffma2(a1[6],u1,wE.x);
                ffma2(a0[7],u0,wE.y); ffma2(a1[7],u1,wE.y);
            }
            #pragma unroll
            for (int h = 0; h < 8; h++) {
                float lo, hi;
                unpack2(a0[h], lo, hi);
                x0[2*h] = fmaxf(lo, 0.0f); x0[2*h+1] = fmaxf(hi, 0.0f);
                unpack2(a1[h], lo, hi);
                x1[2*h] = fmaxf(lo, 0.0f); x1[2*h+1] = fmaxf(hi, 0.0f);
            }
        }

        // ---- Layer 2: x W1 + b1. W1=p[272..527], b1=p[528..543].
        {
            const ulonglong2* bp = (const ulonglong2*)(p + 528);
            #pragma unroll
            for (int h = 0; h < 4; h++) {
                ulonglong2 bv = bp[h];
                a0[2*h]=bv.x; a0[2*h+1]=bv.y;
                a1[2*h]=bv.x; a1[2*h+1]=bv.y;
            }
            #pragma unroll
            for (int d = 0; d < D; d++) {
                const ulonglong2* wr = (const ulonglong2*)(p + 272 + d * D);
                ulonglong2 wA = wr[0], wB = wr[1], wC = wr[2], wE = wr[3];
                unsigned long long u0 = splat2(x0[d]), u1 = splat2(x1[d]);
                ffma2(a0[0],u0,wA.x); ffma2(a1[0],u1,wA.x);
                ffma2(a0[1],u0,wA.y); ffma2(a1[1],u1,wA.y);
                ffma2(a0[2],u0,wB.x); ffma2(a1[2],u1,wB.x);
                ffma2(a0[3],u0,wB.y); ffma2(a1[3],u1,wB.y);
                ffma2(a0[4],u0,wC.x); ffma2(a1[4],u1,wC.x);
                ffma2(a0[5],u0,wC.y); ffma2(a1[5],u1,wC.y);
                ffma2(a0[6],u0,wE.x); ffma2(a1[6],u1,wE.x);
                ffma2(a0[7],u0,wE.y); ffma2(a1[7],u1,wE.y);
            }
        }

        // ---- Relu + write both rows back into the (now-free) x tile slots.
        // Each row is touched only by its owning thread -> no hazard.
        #pragma unroll
        for (int q = 0; q < 4; q++) {
            float l0,h0,l1,h1,l2,h2,l3,h3;
            unpack2(a0[2*q],   l0, h0); unpack2(a0[2*q+1], l1, h1);
            unpack2(a1[2*q],   l2, h2); unpack2(a1[2*q+1], l3, h3);
            float4 v0 = { fmaxf(l0,0.f), fmaxf(h0,0.f), fmaxf(l1,0.f), fmaxf(h1,0.f) };
            float4 v1 = { fmaxf(l2,0.f), fmaxf(h2,0.f), fmaxf(l3,0.f), fmaxf(h3,0.f) };
            *(float4*)(sx + xaddr(r0, q)) = v0;
            *(float4*)(sx + xaddr(r1, q)) = v1;
        }
    }
    __syncthreads();

    // ---- Dense write-out: swizzled LDS.128 -> fully coalesced STG.128.
    {
        float4* dst = (float4*)(out + (size_t)blockIdx.x * CTA_ROWS * D);
        for (int i = t; i < CTA_ROWS * 4; i += THREADS) {
            int row = i >> 2, q = i & 3;
            dst[i] = *(const float4*)(sx + xaddr(row, q));
        }
    }
}

extern "C" void kernel_launch(void* const* d_in, const int* in_sizes, int n_in,
                              void* d_out, int out_size) {
    const float* user_emb = (const float*)d_in[0];
    const float* item_emb = (const float*)d_in[1];
    float* out = (float*)d_out;
    const int B = in_sizes[1] / PARAMS;   // 16384
    can_kernel<<<B / SPC, THREADS>>>(user_emb, item_emb, out);
}